// round 16
// baseline (speedup 1.0000x reference)
#include <cuda_runtime.h>
#include <cuda_fp16.h>
#include <math.h>

// Problem shape: N=100000, E=1600000, F=H1=H2=128, C=40
#define NN 100000
#define EE 1600000

__device__ __half g_hA[(size_t)NN * 128];   // gemm1/gemm2 output (half)
__device__ __half g_hB[(size_t)NN * 128];   // agg output (half), gemm2/3 input
__device__ __half g_h3h[(size_t)NN * 64];   // layer-3 gemm out, packed stride 40
__device__ float  g_dinv[NN];
__device__ int    g_rowptr[NN + 1];
__device__ int    g_cursor[NN];
__device__ int2   g_esw[EE];                // packed (src, dinv[src]) per edge
__device__ int    g_partials[256];
__device__ int    g_is64;

// ---------------- dtype detect + zero counts ----------------
__global__ void k_detect_zero(const int* __restrict__ ei32, int n_check, int N) {
    int i = blockIdx.x * blockDim.x + threadIdx.x;
    if (i < N) g_cursor[i] = 0;
    if (i == 0) {
        int is64 = 1;
        for (int t = 0; t < n_check; t++)
            if (ei32[2 * t + 1] != 0) { is64 = 0; break; }
        g_is64 = is64;
    }
}

__device__ __forceinline__ int load_idx(const void* ei, long long pos) {
    return g_is64 ? (int)((const long long*)ei)[pos] : ((const int*)ei)[pos];
}

__global__ void k_hist(const void* __restrict__ ei, int E, int N) {
    int e = blockIdx.x * blockDim.x + threadIdx.x;
    if (e < E) {
        int d = load_idx(ei, (long long)E + e);
        if ((unsigned)d < (unsigned)N) atomicAdd(&g_cursor[d], 1);
    }
}

template <int NT>
__device__ __forceinline__ int block_exscan(int v) {
    __shared__ int ws[NT / 32];
    int lane = threadIdx.x & 31, wid = threadIdx.x >> 5;
    int x = v;
#pragma unroll
    for (int o = 1; o < 32; o <<= 1) {
        int y = __shfl_up_sync(0xffffffffu, x, o);
        if (lane >= o) x += y;
    }
    if (lane == 31) ws[wid] = x;
    __syncthreads();
    if (wid == 0) {
        int w = (lane < NT / 32) ? ws[lane] : 0;
#pragma unroll
        for (int o = 1; o < 32; o <<= 1) {
            int y = __shfl_up_sync(0xffffffffu, w, o);
            if (lane >= o) w += y;
        }
        if (lane < NT / 32) ws[lane] = w;
    }
    __syncthreads();
    int base = wid ? ws[wid - 1] : 0;
    return base + x - v;
}

// scan1 also computes dinv
__global__ void k_scan1(int N) {
    int gid = blockIdx.x * 512 + threadIdx.x;
    int v = (gid < N) ? g_cursor[gid] : 0;
    if (gid < N) g_dinv[gid] = rsqrtf((float)(v + 1));
    int ex = block_exscan<512>(v);
    if (gid < N) g_rowptr[gid] = ex;
    if (threadIdx.x == 511) g_partials[blockIdx.x] = ex + v;
}

__global__ void k_scan2(int NB) {
    int v = (threadIdx.x < NB) ? g_partials[threadIdx.x] : 0;
    int ex = block_exscan<256>(v);
    if (threadIdx.x < NB) g_partials[threadIdx.x] = ex;
}

__global__ void k_scan3(int N, int E) {
    int gid = blockIdx.x * 512 + threadIdx.x;
    if (gid < N) {
        int r = g_rowptr[gid] + g_partials[blockIdx.x];
        g_rowptr[gid] = r;
        g_cursor[gid] = r;
    }
    if (gid == 0) g_rowptr[N] = E;
}

__global__ void k_scatter(const void* __restrict__ ei, int E, int N) {
    int e = blockIdx.x * blockDim.x + threadIdx.x;
    if (e < E) {
        int s = load_idx(ei, e);
        int d = load_idx(ei, (long long)E + e);
        if ((unsigned)d < (unsigned)N && (unsigned)s < (unsigned)N) {
            int p = atomicAdd(&g_cursor[d], 1);
            if ((unsigned)p < (unsigned)EE)
                g_esw[p] = make_int2(s, __float_as_int(g_dinv[s]));
        }
    }
}

// ---------------- GEMM: C_half = A @ W over rows [m_begin, m_end) ---------------
template <typename TA, int BN, int TN>
__global__ __launch_bounds__(256, 3) void k_gemm(const TA* __restrict__ A,
                                                 const float* __restrict__ W,
                                                 __half* __restrict__ C, int KW,
                                                 int out_stride, int out_cols,
                                                 int m_begin, int m_end) {
    __shared__ float As[64 * 36];
    __shared__ float Ws[32 * (BN + 4)];
    const int WSP = BN + 4;
    int tid = threadIdx.x;
    int tx = tid & 15, ty = tid >> 4;
    int m0 = m_begin + blockIdx.x * 64;

    float acc[4][TN];
#pragma unroll
    for (int i = 0; i < 4; i++)
#pragma unroll
        for (int j = 0; j < TN; j++) acc[i][j] = 0.f;

    for (int kc = 0; kc < 128; kc += 32) {
        if (sizeof(TA) == 4) {
#pragma unroll
            for (int t = 0; t < 2; t++) {
                int idx = tid + t * 256;
                int r = idx >> 3;
                int c4 = (idx & 7) * 4;
                float4 v = make_float4(0.f, 0.f, 0.f, 0.f);
                if (m0 + r < m_end)
                    v = *(const float4*)((const float*)A + (size_t)(m0 + r) * 128 + kc + c4);
                *(float4*)&As[r * 36 + c4] = v;
            }
        } else {
            int r = tid >> 2;
            int part = tid & 3;
            uint4 raw = make_uint4(0, 0, 0, 0);
            if (m0 + r < m_end)
                raw = *(const uint4*)((const __half*)A + (size_t)(m0 + r) * 128 + kc + part * 8);
            const __half2* hp = (const __half2*)&raw;
            float f[8];
#pragma unroll
            for (int i = 0; i < 4; i++) {
                float2 ff = __half22float2(hp[i]);
                f[2 * i] = ff.x;
                f[2 * i + 1] = ff.y;
            }
            *(float4*)&As[r * 36 + part * 8] = make_float4(f[0], f[1], f[2], f[3]);
            *(float4*)&As[r * 36 + part * 8 + 4] = make_float4(f[4], f[5], f[6], f[7]);
        }
        if (KW == BN) {
#pragma unroll
            for (int t = 0; t < (32 * BN) / 1024; t++) {
                int idx = tid + t * 256;
                int k = idx / (BN / 4);
                int c4 = (idx % (BN / 4)) * 4;
                float4 v = *(const float4*)(W + (size_t)(kc + k) * KW + c4);
                *(float4*)&Ws[k * WSP + c4] = v;
            }
        } else {
#pragma unroll
            for (int t = 0; t < (32 * BN) / 256; t++) {
                int idx = tid + t * 256;
                int k = idx / BN, c = idx % BN;
                Ws[k * WSP + c] = (c < KW) ? W[(size_t)(kc + k) * KW + c] : 0.f;
            }
        }
        __syncthreads();
#pragma unroll 4
        for (int k = 0; k < 32; k++) {
            float a[4];
#pragma unroll
            for (int i = 0; i < 4; i++) a[i] = As[(ty * 4 + i) * 36 + k];
            float w[TN];
#pragma unroll
            for (int q = 0; q < TN; q += 4) {
                float4 wv = *(const float4*)&Ws[k * WSP + tx * TN + q];
                w[q] = wv.x; w[q + 1] = wv.y; w[q + 2] = wv.z; w[q + 3] = wv.w;
            }
#pragma unroll
            for (int i = 0; i < 4; i++)
#pragma unroll
                for (int j = 0; j < TN; j++) acc[i][j] += a[i] * w[j];
        }
        __syncthreads();
    }
#pragma unroll
    for (int i = 0; i < 4; i++) {
        int r = m0 + ty * 4 + i;
        int c0 = tx * TN;
        if (r < m_end && c0 < out_cols) {
            __half hb[TN];
#pragma unroll
            for (int j = 0; j < TN; j++) hb[j] = __float2half(acc[i][j]);
            if (TN == 8)
                *(uint4*)(C + (size_t)r * out_stride + c0) = *(uint4*)hb;
            else
                *(uint2*)(C + (size_t)r * out_stride + c0) = *(uint2*)hb;
        }
    }
}

// ---------------- Aggregation (128 feat): warp/node over [n0, n1) --------------
__global__ __launch_bounds__(256) void k_agg128(const __half* __restrict__ h,
                                                const float* __restrict__ bias,
                                                __half* __restrict__ out,
                                                int n0, int n1) {
    int node = n0 + ((blockIdx.x * blockDim.x + threadIdx.x) >> 5);
    if (node >= n1) return;
    int lane = threadIdx.x & 31;
    const uint2* h2 = (const uint2*)h;
    int beg = g_rowptr[node], end = g_rowptr[node + 1];
    float dd = g_dinv[node];

    float ax = 0, ay = 0, az = 0, aw = 0;
    float bx = 0, by = 0, bz = 0, bw = 0;
    for (int e = beg; e < end; e += 16) {
        int cnt = end - e;  // >= 1
        int s[16];
        float wgt[16];
#pragma unroll
        for (int q = 0; q < 16; q++) {
            if (q < cnt) {
                int2 ew = g_esw[e + q];
                s[q] = ew.x;
                wgt[q] = __int_as_float(ew.y);
            } else {
                s[q] = node;
                wgt[q] = 0.f;
            }
        }
        uint2 raw[16];
#pragma unroll
        for (int q = 0; q < 16; q++) raw[q] = h2[(size_t)s[q] * 32 + lane];
#pragma unroll
        for (int q = 0; q < 16; q += 2) {
            float2 f0 = __half22float2(*(__half2*)&raw[q].x);
            float2 f1 = __half22float2(*(__half2*)&raw[q].y);
            ax += wgt[q] * f0.x; ay += wgt[q] * f0.y;
            az += wgt[q] * f1.x; aw += wgt[q] * f1.y;
            float2 g0 = __half22float2(*(__half2*)&raw[q + 1].x);
            float2 g1 = __half22float2(*(__half2*)&raw[q + 1].y);
            bx += wgt[q + 1] * g0.x; by += wgt[q + 1] * g0.y;
            bz += wgt[q + 1] * g1.x; bw += wgt[q + 1] * g1.y;
        }
    }
    uint2 rs = h2[(size_t)node * 32 + lane];
    float2 s0 = __half22float2(*(__half2*)&rs.x);
    float2 s1 = __half22float2(*(__half2*)&rs.y);
    ax += bx + dd * s0.x;
    ay += by + dd * s0.y;
    az += bz + dd * s1.x;
    aw += bw + dd * s1.y;
    float4 bb = ((const float4*)bias)[lane];
    float ox = fmaxf(dd * ax + bb.x, 0.f);
    float oy = fmaxf(dd * ay + bb.y, 0.f);
    float oz = fmaxf(dd * az + bb.z, 0.f);
    float ow = fmaxf(dd * aw + bb.w, 0.f);
    __half2 p0 = __floats2half2_rn(ox, oy);
    __half2 p1 = __floats2half2_rn(oz, ow);
    uint2 pk;
    pk.x = *(unsigned*)&p0;
    pk.y = *(unsigned*)&p1;
    ((uint2*)out)[(size_t)node * 32 + lane] = pk;
}

// ---------------- Aggregation (40 feat, packed stride 40) + log_softmax ---------
__global__ __launch_bounds__(256) void k_agg40(const __half* __restrict__ h,
                                               const float* __restrict__ bias,
                                               float* __restrict__ out, int N) {
    int node = (blockIdx.x * blockDim.x + threadIdx.x) >> 5;
    if (node >= N) return;
    int lane = threadIdx.x & 31;
    const unsigned* h1 = (const unsigned*)h;
    int beg = g_rowptr[node], end = g_rowptr[node + 1];
    bool act = lane < 20;
    float a0 = 0.f, a1 = 0.f;
    for (int e = beg; e < end; e += 16) {
        int cnt = end - e;
        int s[16];
        float wgt[16];
#pragma unroll
        for (int q = 0; q < 16; q++) {
            if (q < cnt) {
                int2 ew = g_esw[e + q];
                s[q] = ew.x;
                wgt[q] = __int_as_float(ew.y);
            } else {
                s[q] = node;
                wgt[q] = 0.f;
            }
        }
        unsigned raw[16];
#pragma unroll
        for (int q = 0; q < 16; q++) raw[q] = act ? h1[(size_t)s[q] * 20 + lane] : 0u;
#pragma unroll
        for (int q = 0; q < 16; q++) {
            float2 f = __half22float2(*(__half2*)&raw[q]);
            a0 += wgt[q] * f.x;
            a1 += wgt[q] * f.y;
        }
    }
    float dd = g_dinv[node];
    unsigned rs = act ? h1[(size_t)node * 20 + lane] : 0u;
    float2 fs = __half22float2(*(__half2*)&rs);
    a0 += dd * fs.x;
    a1 += dd * fs.y;
    float l0 = -3.4e38f, l1 = -3.4e38f;
    if (act) {
        l0 = dd * a0 + bias[2 * lane];
        l1 = dd * a1 + bias[2 * lane + 1];
    }
    float m = fmaxf(l0, l1);
#pragma unroll
    for (int o = 16; o; o >>= 1) m = fmaxf(m, __shfl_xor_sync(0xffffffffu, m, o));
    float s = act ? (expf(l0 - m) + expf(l1 - m)) : 0.f;
#pragma unroll
    for (int o = 16; o; o >>= 1) s += __shfl_xor_sync(0xffffffffu, s, o);
    float ls = logf(s);
    if (act) {
        out[(size_t)node * 40 + 2 * lane] = l0 - m - ls;
        out[(size_t)node * 40 + 2 * lane + 1] = l1 - m - ls;
    }
}

// ---------------- host launcher: fork-join two-stream pipeline ------------------
extern "C" void kernel_launch(void* const* d_in, const int* in_sizes, int n_in,
                              void* d_out, int out_size) {
    const float* x = (const float*)d_in[0];
    const void* ei = d_in[1];
    const float* W1 = (const float*)d_in[2];
    const float* b1 = (const float*)d_in[3];
    const float* W2 = (const float*)d_in[4];
    const float* b2 = (const float*)d_in[5];
    const float* W3 = (const float*)d_in[6];
    const float* b3 = (const float*)d_in[7];

    int N = in_sizes[0] / 128;
    int E = in_sizes[1] / 2;

    int NB = (N + 511) / 512;
    int EB = (E + 255) / 256;
    int NH = (N >> 7) << 6;          // 64-aligned half split
    int GH1 = NH / 64;               // gemm tiles for [0, NH)
    int GH2 = (N - NH + 63) / 64;    // gemm tiles for [NH, N)
    int AH1 = (NH + 7) / 8;          // agg blocks for [0, NH)
    int AH2 = (N - NH + 7) / 8;      // agg blocks for [NH, N)
    int AB = (N + 7) / 8;

    cudaStream_t s1 = 0;                     // legacy default (capture origin)
    cudaStream_t s2 = cudaStreamPerThread;   // second captured stream
    cudaEvent_t e0, eG1, eA1, eG2, eA2, eG3;
    cudaEventCreateWithFlags(&e0, cudaEventDisableTiming);
    cudaEventCreateWithFlags(&eG1, cudaEventDisableTiming);
    cudaEventCreateWithFlags(&eA1, cudaEventDisableTiming);
    cudaEventCreateWithFlags(&eG2, cudaEventDisableTiming);
    cudaEventCreateWithFlags(&eA2, cudaEventDisableTiming);
    cudaEventCreateWithFlags(&eG3, cudaEventDisableTiming);

    // Fork: gemm1 (independent of CSR) runs on s2 concurrent with CSR build.
    k_detect_zero<<<NB, 512, 0, s1>>>((const int*)ei, 64, N);
    cudaEventRecord(e0, s1);
    cudaStreamWaitEvent(s2, e0, 0);
    k_gemm<float, 128, 8><<<(N + 63) / 64, 256, 0, s2>>>(x, W1, g_hA, 128, 128, 128, 0, N);
    cudaEventRecord(eG1, s2);

    k_hist<<<EB, 256, 0, s1>>>(ei, E, N);
    k_scan1<<<NB, 512, 0, s1>>>(N);
    k_scan2<<<1, 256, 0, s1>>>(NB);
    k_scan3<<<NB, 512, 0, s1>>>(N, E);
    k_scatter<<<EB, 256, 0, s1>>>(ei, E, N);
    cudaStreamWaitEvent(s1, eG1, 0);

    // Layer 1 agg halves; gemm2 half-1 overlaps agg half-2.
    k_agg128<<<AH1, 256, 0, s1>>>(g_hA, b1, g_hB, 0, NH);
    cudaEventRecord(eA1, s1);
    k_agg128<<<AH2, 256, 0, s1>>>(g_hA, b1, g_hB, NH, N);
    cudaStreamWaitEvent(s2, eA1, 0);
    k_gemm<__half, 128, 8><<<GH1, 256, 0, s2>>>(g_hB, W2, g_hA, 128, 128, 128, 0, NH);
    cudaEventRecord(eG2, s2);
    k_gemm<__half, 128, 8><<<GH2, 256, 0, s1>>>(g_hB, W2, g_hA, 128, 128, 128, NH, N);
    cudaStreamWaitEvent(s1, eG2, 0);

    // Layer 2 agg halves; gemm3 half-1 overlaps agg half-2.
    k_agg128<<<AH1, 256, 0, s1>>>(g_hA, b2, g_hB, 0, NH);
    cudaEventRecord(eA2, s1);
    k_agg128<<<AH2, 256, 0, s1>>>(g_hA, b2, g_hB, NH, N);
    cudaStreamWaitEvent(s2, eA2, 0);
    k_gemm<__half, 64, 4><<<GH1, 256, 0, s2>>>(g_hB, W3, g_h3h, 40, 40, 40, 0, NH);
    cudaEventRecord(eG3, s2);
    k_gemm<__half, 64, 4><<<GH2, 256, 0, s1>>>(g_hB, W3, g_h3h, 40, 40, 40, NH, N);
    cudaStreamWaitEvent(s1, eG3, 0);   // join s2 back into origin

    // Final fused aggregation + log_softmax (needs all of g_h3h).
    k_agg40<<<AB, 256, 0, s1>>>(g_h3h, b3, (float*)d_out, N);
}

// round 17
// speedup vs baseline: 1.0132x; 1.0132x over previous
#include <cuda_runtime.h>
#include <cuda_fp16.h>
#include <math.h>

// Problem shape: N=100000, E=1600000, F=H1=H2=128, C=40
#define NN 100000
#define EE 1600000

__device__ __half g_hA[(size_t)NN * 128];   // gemm1/gemm2 out (pre-scaled by dinv)
__device__ __half g_hB[(size_t)NN * 128];   // agg output (half), gemm2/3 input
__device__ __half g_h3h[(size_t)NN * 64];   // layer-3 gemm out, packed stride 40
__device__ float  g_dinv[NN];
__device__ int    g_rowptr[NN + 1];
__device__ int    g_cursor[NN];
__device__ int    g_esrc[EE];
__device__ int    g_partials[256];
__device__ int    g_is64;

// ---------------- dtype detect + zero counts ----------------
__global__ void k_detect_zero(const int* __restrict__ ei32, int n_check, int N) {
    int i = blockIdx.x * blockDim.x + threadIdx.x;
    if (i < N) g_cursor[i] = 0;
    if (i == 0) {
        int is64 = 1;
        for (int t = 0; t < n_check; t++)
            if (ei32[2 * t + 1] != 0) { is64 = 0; break; }
        g_is64 = is64;
    }
}

__device__ __forceinline__ int load_idx(const void* ei, long long pos) {
    return g_is64 ? (int)((const long long*)ei)[pos] : ((const int*)ei)[pos];
}

__global__ void k_hist(const void* __restrict__ ei, int E, int N) {
    int e = blockIdx.x * blockDim.x + threadIdx.x;
    if (e < E) {
        int d = load_idx(ei, (long long)E + e);
        if ((unsigned)d < (unsigned)N) atomicAdd(&g_cursor[d], 1);
    }
}

template <int NT>
__device__ __forceinline__ int block_exscan(int v) {
    __shared__ int ws[NT / 32];
    int lane = threadIdx.x & 31, wid = threadIdx.x >> 5;
    int x = v;
#pragma unroll
    for (int o = 1; o < 32; o <<= 1) {
        int y = __shfl_up_sync(0xffffffffu, x, o);
        if (lane >= o) x += y;
    }
    if (lane == 31) ws[wid] = x;
    __syncthreads();
    if (wid == 0) {
        int w = (lane < NT / 32) ? ws[lane] : 0;
#pragma unroll
        for (int o = 1; o < 32; o <<= 1) {
            int y = __shfl_up_sync(0xffffffffu, w, o);
            if (lane >= o) w += y;
        }
        if (lane < NT / 32) ws[lane] = w;
    }
    __syncthreads();
    int base = wid ? ws[wid - 1] : 0;
    return base + x - v;
}

// scan1 also computes dinv
__global__ void k_scan1(int N) {
    int gid = blockIdx.x * 512 + threadIdx.x;
    int v = (gid < N) ? g_cursor[gid] : 0;
    if (gid < N) g_dinv[gid] = rsqrtf((float)(v + 1));
    int ex = block_exscan<512>(v);
    if (gid < N) g_rowptr[gid] = ex;
    if (threadIdx.x == 511) g_partials[blockIdx.x] = ex + v;
}

__global__ void k_scan2(int NB) {
    int v = (threadIdx.x < NB) ? g_partials[threadIdx.x] : 0;
    int ex = block_exscan<256>(v);
    if (threadIdx.x < NB) g_partials[threadIdx.x] = ex;
}

__global__ void k_scan3(int N, int E) {
    int gid = blockIdx.x * 512 + threadIdx.x;
    if (gid < N) {
        int r = g_rowptr[gid] + g_partials[blockIdx.x];
        g_rowptr[gid] = r;
        g_cursor[gid] = r;
    }
    if (gid == 0) g_rowptr[N] = E;
}

__global__ void k_scatter(const void* __restrict__ ei, int E, int N) {
    int e = blockIdx.x * blockDim.x + threadIdx.x;
    if (e < E) {
        int s = load_idx(ei, e);
        int d = load_idx(ei, (long long)E + e);
        if ((unsigned)d < (unsigned)N && (unsigned)s < (unsigned)N) {
            int p = atomicAdd(&g_cursor[d], 1);
            if ((unsigned)p < (unsigned)EE) g_esrc[p] = s;
        }
    }
}

// ---------------- GEMM: C_half[r] = dinv[r] * (A[r] @ W), fp32 accumulate --------
template <typename TA, int BN, int TN>
__global__ __launch_bounds__(256, 3) void k_gemm(const TA* __restrict__ A,
                                                 const float* __restrict__ W,
                                                 __half* __restrict__ C, int N, int KW,
                                                 int out_stride, int out_cols) {
    __shared__ float As[64 * 36];
    __shared__ float Ws[32 * (BN + 4)];
    const int WSP = BN + 4;
    int tid = threadIdx.x;
    int tx = tid & 15, ty = tid >> 4;
    int m0 = blockIdx.x * 64;

    float acc[4][TN];
#pragma unroll
    for (int i = 0; i < 4; i++)
#pragma unroll
        for (int j = 0; j < TN; j++) acc[i][j] = 0.f;

    for (int kc = 0; kc < 128; kc += 32) {
        if (sizeof(TA) == 4) {
#pragma unroll
            for (int t = 0; t < 2; t++) {
                int idx = tid + t * 256;
                int r = idx >> 3;
                int c4 = (idx & 7) * 4;
                float4 v = make_float4(0.f, 0.f, 0.f, 0.f);
                if (m0 + r < N)
                    v = *(const float4*)((const float*)A + (size_t)(m0 + r) * 128 + kc + c4);
                *(float4*)&As[r * 36 + c4] = v;
            }
        } else {
            int r = tid >> 2;
            int part = tid & 3;
            uint4 raw = make_uint4(0, 0, 0, 0);
            if (m0 + r < N)
                raw = *(const uint4*)((const __half*)A + (size_t)(m0 + r) * 128 + kc + part * 8);
            const __half2* hp = (const __half2*)&raw;
            float f[8];
#pragma unroll
            for (int i = 0; i < 4; i++) {
                float2 ff = __half22float2(hp[i]);
                f[2 * i] = ff.x;
                f[2 * i + 1] = ff.y;
            }
            *(float4*)&As[r * 36 + part * 8] = make_float4(f[0], f[1], f[2], f[3]);
            *(float4*)&As[r * 36 + part * 8 + 4] = make_float4(f[4], f[5], f[6], f[7]);
        }
        if (KW == BN) {
#pragma unroll
            for (int t = 0; t < (32 * BN) / 1024; t++) {
                int idx = tid + t * 256;
                int k = idx / (BN / 4);
                int c4 = (idx % (BN / 4)) * 4;
                float4 v = *(const float4*)(W + (size_t)(kc + k) * KW + c4);
                *(float4*)&Ws[k * WSP + c4] = v;
            }
        } else {
#pragma unroll
            for (int t = 0; t < (32 * BN) / 256; t++) {
                int idx = tid + t * 256;
                int k = idx / BN, c = idx % BN;
                Ws[k * WSP + c] = (c < KW) ? W[(size_t)(kc + k) * KW + c] : 0.f;
            }
        }
        __syncthreads();
#pragma unroll 4
        for (int k = 0; k < 32; k++) {
            float a[4];
#pragma unroll
            for (int i = 0; i < 4; i++) a[i] = As[(ty * 4 + i) * 36 + k];
            float w[TN];
#pragma unroll
            for (int q = 0; q < TN; q += 4) {
                float4 wv = *(const float4*)&Ws[k * WSP + tx * TN + q];
                w[q] = wv.x; w[q + 1] = wv.y; w[q + 2] = wv.z; w[q + 3] = wv.w;
            }
#pragma unroll
            for (int i = 0; i < 4; i++)
#pragma unroll
                for (int j = 0; j < TN; j++) acc[i][j] += a[i] * w[j];
        }
        __syncthreads();
    }
#pragma unroll
    for (int i = 0; i < 4; i++) {
        int r = m0 + ty * 4 + i;
        int c0 = tx * TN;
        if (r < N && c0 < out_cols) {
            float sc = g_dinv[r];   // pre-scale row by dinv[r]
            __half hb[TN];
#pragma unroll
            for (int j = 0; j < TN; j++) hb[j] = __float2half(sc * acc[i][j]);
            if (TN == 8)
                *(uint4*)(C + (size_t)r * out_stride + c0) = *(uint4*)hb;
            else
                *(uint2*)(C + (size_t)r * out_stride + c0) = *(uint2*)hb;
        }
    }
}

// ---------------- Aggregation (128 feat): plain sum of pre-scaled rows ----------
// out[d] = relu(dinv[d] * (sum_{s in adj(d)} h'[s] + h'[d]) + bias), h' = dinv*h.
__global__ __launch_bounds__(256) void k_agg128(const __half* __restrict__ h,
                                                const float* __restrict__ bias,
                                                __half* __restrict__ out, int N) {
    int node = (blockIdx.x * blockDim.x + threadIdx.x) >> 5;
    if (node >= N) return;
    int lane = threadIdx.x & 31;
    const uint2* h2 = (const uint2*)h;
    int beg = g_rowptr[node], end = g_rowptr[node + 1];

    float ax = 0, ay = 0, az = 0, aw = 0;
    float bx = 0, by = 0, bz = 0, bw = 0;
    for (int e = beg; e < end; e += 16) {
        int cnt = end - e;  // >= 1
        int s[16];
        float msk[16];
#pragma unroll
        for (int q = 0; q < 16; q++) {
            s[q] = (q < cnt) ? g_esrc[e + q] : node;
            msk[q] = (q < cnt) ? 1.f : 0.f;
        }
        uint2 raw[16];
#pragma unroll
        for (int q = 0; q < 16; q++) raw[q] = h2[(size_t)s[q] * 32 + lane];
#pragma unroll
        for (int q = 0; q < 16; q += 2) {
            float2 f0 = __half22float2(*(__half2*)&raw[q].x);
            float2 f1 = __half22float2(*(__half2*)&raw[q].y);
            ax += msk[q] * f0.x; ay += msk[q] * f0.y;
            az += msk[q] * f1.x; aw += msk[q] * f1.y;
            float2 g0 = __half22float2(*(__half2*)&raw[q + 1].x);
            float2 g1 = __half22float2(*(__half2*)&raw[q + 1].y);
            bx += msk[q + 1] * g0.x; by += msk[q + 1] * g0.y;
            bz += msk[q + 1] * g1.x; bw += msk[q + 1] * g1.y;
        }
    }
    // self loop (row already pre-scaled by dinv[node])
    uint2 rs = h2[(size_t)node * 32 + lane];
    float2 s0 = __half22float2(*(__half2*)&rs.x);
    float2 s1 = __half22float2(*(__half2*)&rs.y);
    ax += bx + s0.x;
    ay += by + s0.y;
    az += bz + s1.x;
    aw += bw + s1.y;
    float dd = g_dinv[node];
    float4 bb = ((const float4*)bias)[lane];
    float ox = fmaxf(dd * ax + bb.x, 0.f);
    float oy = fmaxf(dd * ay + bb.y, 0.f);
    float oz = fmaxf(dd * az + bb.z, 0.f);
    float ow = fmaxf(dd * aw + bb.w, 0.f);
    __half2 p0 = __floats2half2_rn(ox, oy);
    __half2 p1 = __floats2half2_rn(oz, ow);
    uint2 pk;
    pk.x = *(unsigned*)&p0;
    pk.y = *(unsigned*)&p1;
    ((uint2*)out)[(size_t)node * 32 + lane] = pk;
}

// ---------------- Aggregation (40 feat, packed stride 40) + log_softmax ---------
__global__ __launch_bounds__(256) void k_agg40(const __half* __restrict__ h,
                                               const float* __restrict__ bias,
                                               float* __restrict__ out, int N) {
    int node = (blockIdx.x * blockDim.x + threadIdx.x) >> 5;
    if (node >= N) return;
    int lane = threadIdx.x & 31;
    const unsigned* h1 = (const unsigned*)h;
    int beg = g_rowptr[node], end = g_rowptr[node + 1];
    bool act = lane < 20;
    float a0 = 0.f, a1 = 0.f;
    for (int e = beg; e < end; e += 16) {
        int cnt = end - e;
        int s[16];
        float msk[16];
#pragma unroll
        for (int q = 0; q < 16; q++) {
            s[q] = (q < cnt) ? g_esrc[e + q] : node;
            msk[q] = (q < cnt) ? 1.f : 0.f;
        }
        unsigned raw[16];
#pragma unroll
        for (int q = 0; q < 16; q++) raw[q] = act ? h1[(size_t)s[q] * 20 + lane] : 0u;
#pragma unroll
        for (int q = 0; q < 16; q++) {
            float2 f = __half22float2(*(__half2*)&raw[q]);
            a0 += msk[q] * f.x;
            a1 += msk[q] * f.y;
        }
    }
    unsigned rs = act ? h1[(size_t)node * 20 + lane] : 0u;
    float2 fs = __half22float2(*(__half2*)&rs);
    a0 += fs.x;
    a1 += fs.y;
    float dd = g_dinv[node];
    float l0 = -3.4e38f, l1 = -3.4e38f;
    if (act) {
        l0 = dd * a0 + bias[2 * lane];
        l1 = dd * a1 + bias[2 * lane + 1];
    }
    float m = fmaxf(l0, l1);
#pragma unroll
    for (int o = 16; o; o >>= 1) m = fmaxf(m, __shfl_xor_sync(0xffffffffu, m, o));
    float s = act ? (expf(l0 - m) + expf(l1 - m)) : 0.f;
#pragma unroll
    for (int o = 16; o; o >>= 1) s += __shfl_xor_sync(0xffffffffu, s, o);
    float ls = logf(s);
    if (act) {
        out[(size_t)node * 40 + 2 * lane] = l0 - m - ls;
        out[(size_t)node * 40 + 2 * lane + 1] = l1 - m - ls;
    }
}

// ---------------- host launcher (single stream; dinv needed before gemm1) -------
extern "C" void kernel_launch(void* const* d_in, const int* in_sizes, int n_in,
                              void* d_out, int out_size) {
    const float* x = (const float*)d_in[0];
    const void* ei = d_in[1];
    const float* W1 = (const float*)d_in[2];
    const float* b1 = (const float*)d_in[3];
    const float* W2 = (const float*)d_in[4];
    const float* b2 = (const float*)d_in[5];
    const float* W3 = (const float*)d_in[6];
    const float* b3 = (const float*)d_in[7];

    int N = in_sizes[0] / 128;
    int E = in_sizes[1] / 2;

    int NB = (N + 511) / 512;
    int EB = (E + 255) / 256;
    int GB = (N + 63) / 64;
    int AB = (N + 7) / 8;

    k_detect_zero<<<NB, 512>>>((const int*)ei, 64, N);
    k_hist<<<EB, 256>>>(ei, E, N);
    k_scan1<<<NB, 512>>>(N);      // produces dinv + rowptr
    k_scan2<<<1, 256>>>(NB);
    k_scan3<<<NB, 512>>>(N, E);
    k_scatter<<<EB, 256>>>(ei, E, N);

    k_gemm<float, 128, 8><<<GB, 256>>>(x, W1, g_hA, N, 128, 128, 128);
    k_agg128<<<AB, 256>>>(g_hA, b1, g_hB, N);
    k_gemm<__half, 128, 8><<<GB, 256>>>(g_hB, W2, g_hA, N, 128, 128, 128);
    k_agg128<<<AB, 256>>>(g_hA, b2, g_hB, N);
    k_gemm<__half, 64, 4><<<GB, 256>>>(g_hB, W3, g_h3h, N, 40, 40, 40);
    k_agg40<<<AB, 256>>>(g_h3h, b3, (float*)d_out, N);
}